// round 4
// baseline (speedup 1.0000x reference)
#include <cuda_runtime.h>
#include <cstdint>

// LocalAggregationLoss — cp.async pipelined gather version.
//   codes:        [1024, 128] fp32
//   memory_bank:  [1000000, 128] fp32
//   idx_background, idx_close: [1024, 200] int32 (JAX default) or int64
//   out[b] = log(sum_k exp(dot(bank[idx_bg[b,k]], v_b)/T))
//          - log(sum_k exp(dot(bank[idx_cl[b,k]], v_b)/T))

#define DIM    128
#define KNEI   200
#define TINV   (1.0f / 0.07f)
#define NWARP  8
#define RPW    (KNEI / NWARP)   // 25 row-pairs per warp
#define DEPTH  4                 // pipeline stages (power of 2)
#define N_BANK 1000000LL

__device__ __forceinline__ void cp_async16(uint32_t smem, const void* gmem)
{
    asm volatile("cp.async.cg.shared.global [%0], [%1], 16;\n"
                 :: "r"(smem), "l"(gmem) : "memory");
}
#define CP_COMMIT() asm volatile("cp.async.commit_group;\n" ::: "memory")
#define CP_WAIT(n)  asm volatile("cp.async.wait_group %0;\n" :: "n"(n) : "memory")

// int64 vs int32 index detection: view first 16B as two int64; real int64
// indices are both in [0,1e6), reinterpreted int32 data isn't (p ~ 1e-12).
__device__ __forceinline__ bool idx_is64(const void* p)
{
    const longlong2 v = *reinterpret_cast<const longlong2*>(p);
    return (v.x >= 0 && v.x < N_BANK) & (v.y >= 0 && v.y < N_BANK);
}

// Per-warp smem ring: DEPTH stages x (2 rows x 128 floats) = 4 KB / warp.
#define STAGE_F (2 * DIM)            // floats per stage (pair of rows)
#define WARP_F  (DEPTH * STAGE_F)    // floats per warp region

__device__ __forceinline__ void pipeline(const float* __restrict__ bank,
                                         long long my_bg, long long my_cl,
                                         float* __restrict__ wbuf,  // warp region
                                         float4 vv, int lane,
                                         float& s1, float& s2)
{
    const uint32_t wbase =
        (uint32_t)__cvta_generic_to_shared(wbuf) + (uint32_t)lane * 16u;

    // ---- prologue: fill DEPTH stages ----
    #pragma unroll
    for (int j = 0; j < DEPTH; ++j) {
        const long long i1 = __shfl_sync(0xffffffffu, my_bg, j);
        const long long i2 = __shfl_sync(0xffffffffu, my_cl, j);
        const uint32_t dst = wbase + (uint32_t)j * (STAGE_F * 4);
        cp_async16(dst,                bank + i1 * DIM + lane * 4);
        cp_async16(dst + DIM * 4,      bank + i2 * DIM + lane * 4);
        CP_COMMIT();
    }

    for (int j = 0; j < RPW; ++j) {
        CP_WAIT(DEPTH - 1);            // oldest stage arrived
        const int s = j & (DEPTH - 1);
        const float4 a = *reinterpret_cast<const float4*>(
            wbuf + s * STAGE_F + lane * 4);
        const float4 g = *reinterpret_cast<const float4*>(
            wbuf + s * STAGE_F + DIM + lane * 4);

        // refill same stage (gmem fetch lands far after the LDS above)
        const int jn = j + DEPTH;
        if (jn < RPW) {
            const long long i1 = __shfl_sync(0xffffffffu, my_bg, jn);
            const long long i2 = __shfl_sync(0xffffffffu, my_cl, jn);
            const uint32_t dst = wbase + (uint32_t)s * (STAGE_F * 4);
            cp_async16(dst,           bank + i1 * DIM + lane * 4);
            cp_async16(dst + DIM * 4, bank + i2 * DIM + lane * 4);
        }
        CP_COMMIT();                   // always commit (possibly empty) to
                                       // keep exactly DEPTH groups pending

        float d1 = a.x * vv.x + a.y * vv.y + a.z * vv.z + a.w * vv.w;
        float d2 = g.x * vv.x + g.y * vv.y + g.z * vv.z + g.w * vv.w;
        #pragma unroll
        for (int o = 16; o; o >>= 1) {
            d1 += __shfl_xor_sync(0xffffffffu, d1, o);
            d2 += __shfl_xor_sync(0xffffffffu, d2, o);
        }
        s1 += __expf(d1 * TINV);
        s2 += __expf(d2 * TINV);
    }
}

__global__ __launch_bounds__(NWARP * 32)
void la_loss_kernel(const float* __restrict__ codes,
                    const float* __restrict__ bank,
                    const void*  __restrict__ idx_bg,
                    const void*  __restrict__ idx_cl,
                    float* __restrict__ out)
{
    const int b    = blockIdx.x;
    const int tid  = threadIdx.x;
    const int wid  = tid >> 5;
    const int lane = tid & 31;

    __shared__ __align__(16) float sbuf[NWARP * WARP_F];   // 32 KB
    __shared__ float red[NWARP];
    __shared__ float s1_sh[NWARP];
    __shared__ float s2_sh[NWARP];

    // ---- normalize code row ----
    float c = 0.0f;
    if (tid < DIM) c = codes[b * DIM + tid];
    float ss = c * c;
    #pragma unroll
    for (int o = 16; o; o >>= 1) ss += __shfl_xor_sync(0xffffffffu, ss, o);
    if (lane == 0) red[wid] = ss;
    __syncthreads();
    float total = 0.0f;
    #pragma unroll
    for (int w = 0; w < NWARP; ++w) total += red[w];
    const float inv_norm = rsqrtf(total);

    // keep v in registers via the smem staging buffer trick: store then read
    __shared__ float v_sh[DIM];
    if (tid < DIM) v_sh[tid] = c * inv_norm;
    __syncthreads();
    const float4 vv = *reinterpret_cast<const float4*>(&v_sh[lane * 4]);

    // ---- prefetch this warp's 25+25 indices into lane registers ----
    long long my_bg = 0, my_cl = 0;
    const long long base = (long long)b * KNEI + wid * RPW;
    if (idx_is64(idx_bg)) {
        if (lane < RPW) {
            my_bg = ((const long long*)idx_bg)[base + lane];
            my_cl = ((const long long*)idx_cl)[base + lane];
        }
    } else {
        if (lane < RPW) {
            my_bg = (long long)((const int*)idx_bg)[base + lane];
            my_cl = (long long)((const int*)idx_cl)[base + lane];
        }
    }

    float s1 = 0.0f, s2 = 0.0f;
    pipeline(bank, my_bg, my_cl, sbuf + wid * WARP_F, vv, lane, s1, s2);

    if (lane == 0) { s1_sh[wid] = s1; s2_sh[wid] = s2; }
    __syncthreads();

    if (tid == 0) {
        float S1 = 0.0f, S2 = 0.0f;
        #pragma unroll
        for (int w = 0; w < NWARP; ++w) { S1 += s1_sh[w]; S2 += s2_sh[w]; }
        out[b] = __logf(S1) - __logf(S2);
    }
}

extern "C" void kernel_launch(void* const* d_in, const int* in_sizes, int n_in,
                              void* d_out, int out_size)
{
    const float* codes  = (const float*)d_in[0];
    const float* bank   = (const float*)d_in[1];
    const void*  idx_bg = d_in[2];
    const void*  idx_cl = d_in[3];
    float*       out    = (float*)d_out;

    la_loss_kernel<<<1024, NWARP * 32>>>(codes, bank, idx_bg, idx_cl, out);
}

// round 5
// speedup vs baseline: 1.1067x; 1.1067x over previous
#include <cuda_runtime.h>

// LocalAggregationLoss — register-batched gather, MLP=10 per warp.
//   codes:        [1024, 128] fp32
//   memory_bank:  [1000000, 128] fp32
//   idx_background, idx_close: [1024, 200] int32 (JAX default) or int64
//   out[b] = log(sum_k exp(dot(bank[idx_bg[b,k]], v_b)/T))
//          - log(sum_k exp(dot(bank[idx_cl[b,k]], v_b)/T))

#define DIM    128
#define KNEI   200
#define TINV   (1.0f / 0.07f)
#define NWARP  4
#define RPW    (KNEI / NWARP)   // 50 row-pairs per warp
#define BATCH5 5                 // pairs per register batch (MLP = 10)
#define N_BANK 1000000LL

// int64 vs int32 detection: first 16B as two int64 must both be in [0,1e6).
__device__ __forceinline__ bool idx_is64(const void* p)
{
    const longlong2 v = *reinterpret_cast<const longlong2*>(p);
    return (v.x >= 0 && v.x < N_BANK) & (v.y >= 0 && v.y < N_BANK);
}

template <typename IdxT>
__device__ __forceinline__ void accumulate(const float* __restrict__ bank,
                                           const IdxT* __restrict__ ibg,
                                           const IdxT* __restrict__ icl,
                                           float4 vv, int lane,
                                           float& s1, float& s2)
{
    #pragma unroll 1
    for (int t = 0; t < RPW / BATCH5; ++t) {
        float4 a[BATCH5], g[BATCH5];

        // ---- load phase: 10 independent 512B gathers in flight ----
        #pragma unroll
        for (int u = 0; u < BATCH5; ++u) {
            const long long i1 = (long long)ibg[t * BATCH5 + u];
            const long long i2 = (long long)icl[t * BATCH5 + u];
            a[u] = __ldg(reinterpret_cast<const float4*>(
                       bank + i1 * DIM + lane * 4));
            g[u] = __ldg(reinterpret_cast<const float4*>(
                       bank + i2 * DIM + lane * 4));
        }

        // ---- compute phase ----
        #pragma unroll
        for (int u = 0; u < BATCH5; ++u) {
            float d1 = a[u].x * vv.x + a[u].y * vv.y
                     + a[u].z * vv.z + a[u].w * vv.w;
            float d2 = g[u].x * vv.x + g[u].y * vv.y
                     + g[u].z * vv.z + g[u].w * vv.w;
            #pragma unroll
            for (int o = 16; o; o >>= 1) {
                d1 += __shfl_xor_sync(0xffffffffu, d1, o);
                d2 += __shfl_xor_sync(0xffffffffu, d2, o);
            }
            s1 += __expf(d1 * TINV);
            s2 += __expf(d2 * TINV);
        }
    }
}

__global__ __launch_bounds__(NWARP * 32, 6)
void la_loss_kernel(const float* __restrict__ codes,
                    const float* __restrict__ bank,
                    const void*  __restrict__ idx_bg,
                    const void*  __restrict__ idx_cl,
                    float* __restrict__ out)
{
    const int b    = blockIdx.x;
    const int tid  = threadIdx.x;
    const int wid  = tid >> 5;
    const int lane = tid & 31;

    __shared__ float v_sh[DIM];
    __shared__ float red[NWARP];
    __shared__ float s1_sh[NWARP];
    __shared__ float s2_sh[NWARP];

    // ---- normalize code row (128 threads = 128 elements) ----
    float c = codes[b * DIM + tid];
    float ss = c * c;
    #pragma unroll
    for (int o = 16; o; o >>= 1) ss += __shfl_xor_sync(0xffffffffu, ss, o);
    if (lane == 0) red[wid] = ss;
    __syncthreads();
    float total = 0.0f;
    #pragma unroll
    for (int w = 0; w < NWARP; ++w) total += red[w];
    const float inv_norm = rsqrtf(total);
    v_sh[tid] = c * inv_norm;
    __syncthreads();

    const float4 vv = *reinterpret_cast<const float4*>(&v_sh[lane * 4]);

    float s1 = 0.0f, s2 = 0.0f;
    const long long base = (long long)b * KNEI + wid * RPW;

    if (idx_is64(idx_bg)) {
        accumulate<long long>(bank,
                              (const long long*)idx_bg + base,
                              (const long long*)idx_cl + base,
                              vv, lane, s1, s2);
    } else {
        accumulate<int>(bank,
                        (const int*)idx_bg + base,
                        (const int*)idx_cl + base,
                        vv, lane, s1, s2);
    }

    if (lane == 0) { s1_sh[wid] = s1; s2_sh[wid] = s2; }
    __syncthreads();

    if (tid == 0) {
        float S1 = 0.0f, S2 = 0.0f;
        #pragma unroll
        for (int w = 0; w < NWARP; ++w) { S1 += s1_sh[w]; S2 += s2_sh[w]; }
        out[b] = __logf(S1) - __logf(S2);
    }
}

extern "C" void kernel_launch(void* const* d_in, const int* in_sizes, int n_in,
                              void* d_out, int out_size)
{
    const float* codes  = (const float*)d_in[0];
    const float* bank   = (const float*)d_in[1];
    const void*  idx_bg = d_in[2];
    const void*  idx_cl = d_in[3];
    float*       out    = (float*)d_out;

    la_loss_kernel<<<1024, NWARP * 32>>>(codes, bank, idx_bg, idx_cl, out);
}

// round 6
// speedup vs baseline: 1.1078x; 1.0010x over previous
#include <cuda_runtime.h>
#include <cstdint>

// LocalAggregationLoss — register-batched gather, MLP=10, pipelined indices,
// single-wave launch (7 CTAs/SM x 148 SMs >= 1024 CTAs).
//   codes:        [1024, 128] fp32
//   memory_bank:  [1000000, 128] fp32
//   idx_background, idx_close: [1024, 200] int32 (JAX default) or int64
//   out[b] = log(sum_k exp(dot(bank[idx_bg[b,k]], v_b)/T))
//          - log(sum_k exp(dot(bank[idx_cl[b,k]], v_b)/T))

#define DIM    128
#define KNEI   200
#define TINV   (1.0f / 0.07f)
#define NWARP  4
#define RPW    (KNEI / NWARP)   // 50 row-pairs per warp
#define BATCH5 5                 // pairs per register batch (MLP = 10)
#define NBATCH (RPW / BATCH5)    // 10 batches
#define N_BANK 1000000LL

// int64 vs int32 detection: first 16B as two int64 must both be in [0,1e6).
__device__ __forceinline__ bool idx_is64(const void* p)
{
    const longlong2 v = *reinterpret_cast<const longlong2*>(p);
    return (v.x >= 0 && v.x < N_BANK) & (v.y >= 0 && v.y < N_BANK);
}

template <typename IdxT>
__device__ __forceinline__ void accumulate(const float* __restrict__ bank,
                                           const IdxT* __restrict__ ibg,
                                           const IdxT* __restrict__ icl,
                                           float4 vv, int lane,
                                           float& s1, float& s2)
{
    // base pointer already includes this lane's 16B slice
    const char* base = reinterpret_cast<const char*>(bank)
                     + (uint32_t)(lane * 16);

    // byte offsets fit in u32: idx*512 <= 5.12e8 < 2^32
    uint32_t o1[BATCH5], o2[BATCH5];
    #pragma unroll
    for (int u = 0; u < BATCH5; ++u) {
        o1[u] = (uint32_t)ibg[u] * 512u;
        o2[u] = (uint32_t)icl[u] * 512u;
    }

    #pragma unroll 1
    for (int t = 0; t < NBATCH; ++t) {
        float4 a[BATCH5], g[BATCH5];

        // ---- issue 10 independent 512B gathers from register offsets ----
        #pragma unroll
        for (int u = 0; u < BATCH5; ++u) {
            a[u] = __ldg(reinterpret_cast<const float4*>(base + o1[u]));
            g[u] = __ldg(reinterpret_cast<const float4*>(base + o2[u]));
        }

        // ---- prefetch next batch's indices (overlaps with gathers) ----
        if (t + 1 < NBATCH) {
            #pragma unroll
            for (int u = 0; u < BATCH5; ++u) {
                o1[u] = (uint32_t)ibg[(t + 1) * BATCH5 + u] * 512u;
                o2[u] = (uint32_t)icl[(t + 1) * BATCH5 + u] * 512u;
            }
        }

        // ---- compute ----
        #pragma unroll
        for (int u = 0; u < BATCH5; ++u) {
            float d1 = a[u].x * vv.x + a[u].y * vv.y
                     + a[u].z * vv.z + a[u].w * vv.w;
            float d2 = g[u].x * vv.x + g[u].y * vv.y
                     + g[u].z * vv.z + g[u].w * vv.w;
            #pragma unroll
            for (int o = 16; o; o >>= 1) {
                d1 += __shfl_xor_sync(0xffffffffu, d1, o);
                d2 += __shfl_xor_sync(0xffffffffu, d2, o);
            }
            s1 += __expf(d1 * TINV);
            s2 += __expf(d2 * TINV);
        }
    }
}

__global__ __launch_bounds__(NWARP * 32, 7)
void la_loss_kernel(const float* __restrict__ codes,
                    const float* __restrict__ bank,
                    const void*  __restrict__ idx_bg,
                    const void*  __restrict__ idx_cl,
                    float* __restrict__ out)
{
    const int b    = blockIdx.x;
    const int tid  = threadIdx.x;
    const int wid  = tid >> 5;
    const int lane = tid & 31;

    __shared__ float v_sh[DIM];
    __shared__ float red[NWARP];
    __shared__ float s1_sh[NWARP];
    __shared__ float s2_sh[NWARP];

    // ---- normalize code row (128 threads = 128 elements) ----
    float c = codes[b * DIM + tid];
    float ss = c * c;
    #pragma unroll
    for (int o = 16; o; o >>= 1) ss += __shfl_xor_sync(0xffffffffu, ss, o);
    if (lane == 0) red[wid] = ss;
    __syncthreads();
    float total = 0.0f;
    #pragma unroll
    for (int w = 0; w < NWARP; ++w) total += red[w];
    const float inv_norm = rsqrtf(total);
    v_sh[tid] = c * inv_norm;
    __syncthreads();

    const float4 vv = *reinterpret_cast<const float4*>(&v_sh[lane * 4]);

    float s1 = 0.0f, s2 = 0.0f;
    const long long base = (long long)b * KNEI + wid * RPW;

    if (idx_is64(idx_bg)) {
        accumulate<long long>(bank,
                              (const long long*)idx_bg + base,
                              (const long long*)idx_cl + base,
                              vv, lane, s1, s2);
    } else {
        accumulate<int>(bank,
                        (const int*)idx_bg + base,
                        (const int*)idx_cl + base,
                        vv, lane, s1, s2);
    }

    if (lane == 0) { s1_sh[wid] = s1; s2_sh[wid] = s2; }
    __syncthreads();

    if (tid == 0) {
        float S1 = 0.0f, S2 = 0.0f;
        #pragma unroll
        for (int w = 0; w < NWARP; ++w) { S1 += s1_sh[w]; S2 += s2_sh[w]; }
        out[b] = __logf(S1) - __logf(S2);
    }
}

extern "C" void kernel_launch(void* const* d_in, const int* in_sizes, int n_in,
                              void* d_out, int out_size)
{
    const float* codes  = (const float*)d_in[0];
    const float* bank   = (const float*)d_in[1];
    const void*  idx_bg = d_in[2];
    const void*  idx_cl = d_in[3];
    float*       out    = (float*)d_out;

    la_loss_kernel<<<1024, NWARP * 32>>>(codes, bank, idx_bg, idx_cl, out);
}